// round 14
// baseline (speedup 1.0000x reference)
#include <cuda_runtime.h>
#include <cuda_fp16.h>

#define N_NODES 50000
#define N_EDGES 800000
#define DH 64
#define NG 64

#define SCAN_B 512
#define SCAN_NBLK ((N_NODES + SCAN_B - 1) / SCAN_B)   // 98

#define TB 256
#define GE4_BLOCKS ((N_EDGES / 4 + TB - 1) / TB)               // 782 (4 edges/thread)
#define GQ_BLOCKS ((N_NODES / 4 * 16 + TB - 1) / TB)           // 782

// ---------------- device scratch ----------------
__device__ float          g_dinv[N_NODES];
__device__ int            g_degi[N_NODES];   // zero-init; re-zeroed by scan1
__device__ int            g_off[N_NODES + 1];
__device__ int            g_cur[N_NODES];
__device__ int            g_bsum[SCAN_NBLK];
__device__ unsigned short g_edge[N_EDGES];   // src index (fits: N_NODES < 65536)
__device__ uint2          g_t16[N_NODES * 16];
__device__ uint2          g_h16[N_NODES * 16];
__device__ int            g_start[NG + 1];

// packed f32x2 helpers (Blackwell dual-FP32 pipe; PTX-only)
__device__ __forceinline__ unsigned long long pk2(float a, float b) {
    unsigned long long r;
    asm("mov.b64 %0, {%1, %2};" : "=l"(r) : "f"(a), "f"(b));
    return r;
}
__device__ __forceinline__ void fma2(unsigned long long& d,
                                     unsigned long long a, unsigned long long b) {
    asm("fma.rn.f32x2 %0, %1, %2, %0;" : "+l"(d) : "l"(a), "l"(b));
}
__device__ __forceinline__ float2 upk2(unsigned long long v) {
    float2 f;
    asm("mov.b64 {%0, %1}, %2;" : "=f"(f.x), "=f"(f.y) : "l"(v));
    return f;
}
__device__ __forceinline__ void upk_h4(uint2 u, float2& a, float2& b) {
    a = __half22float2(*(const __half2*)&u.x);
    b = __half22float2(*(const __half2*)&u.y);
}
__device__ __forceinline__ uint2 pk_h4(float x, float y, float z, float w) {
    __half2 h01 = __floats2half2_rn(x, y);
    __half2 h23 = __floats2half2_rn(z, w);
    uint2 u;
    u.x = *(const unsigned int*)&h01;
    u.y = *(const unsigned int*)&h23;
    return u;
}

// ---------------- GEMM body (shared by fat kernel and standalone) ---------
template <bool USEH>
__device__ __forceinline__ void gemm_body(const float* __restrict__ in,
                                          const float* __restrict__ W,
                                          int gbid, float4* Ws) {
    const float4* W4 = (const float4*)W;
    for (int i = threadIdx.x; i < DH * 16; i += TB) Ws[i] = W4[i];
    __syncthreads();

    int tid  = gbid * TB + threadIdx.x;
    int quad = tid >> 4;
    int g    = tid & 15;
    int node0 = quad * 4;
    if (node0 >= N_NODES) return;

    unsigned long long acc01[4] = {0, 0, 0, 0};
    unsigned long long acc23[4] = {0, 0, 0, 0};

#pragma unroll
    for (int k4 = 0; k4 < 16; k4++) {
        float4 xv[4];
#pragma unroll
        for (int i = 0; i < 4; i++) {
            if (USEH) {
                float2 a, b;
                upk_h4(g_h16[(node0 + i) * 16 + k4], a, b);
                xv[i] = make_float4(a.x, a.y, b.x, b.y);
            } else {
                xv[i] = ((const float4*)in)[(node0 + i) * 16 + k4];
            }
        }
#pragma unroll
        for (int s = 0; s < 4; s++) {
            float4 w = Ws[(k4 * 4 + s) * 16 + g];
            unsigned long long w01 = pk2(w.x, w.y);
            unsigned long long w23 = pk2(w.z, w.w);
#pragma unroll
            for (int i = 0; i < 4; i++) {
                float xk = (s == 0) ? xv[i].x : (s == 1) ? xv[i].y
                         : (s == 2) ? xv[i].z : xv[i].w;
                unsigned long long xx = pk2(xk, xk);
                fma2(acc01[i], w01, xx);
                fma2(acc23[i], w23, xx);
            }
        }
    }
#pragma unroll
    for (int i = 0; i < 4; i++) {
        float2 lo = upk2(acc01[i]);
        float2 hi = upk2(acc23[i]);
        g_t16[(node0 + i) * 16 + g] = pk_h4(lo.x, lo.y, hi.x, hi.y);
    }
}

// ---------------- fat kernel: degree histogram (4 e/thr) ∥ layer-1 GEMM ---
__global__ void deg_gemm1_kernel(const int* __restrict__ col,
                                 const float* __restrict__ x,
                                 const float* __restrict__ W0) {
    __shared__ float4 Ws[DH * 16];  // 16 KB (gemm half only)
    if (blockIdx.x < GE4_BLOCKS) {
        int base = (blockIdx.x * TB + threadIdx.x) * 4;
        if (base + 3 < N_EDGES) {
            int4 c4 = *(const int4*)(col + base);
            if ((unsigned)c4.x < (unsigned)N_NODES) atomicAdd(&g_degi[c4.x], 1);
            if ((unsigned)c4.y < (unsigned)N_NODES) atomicAdd(&g_degi[c4.y], 1);
            if ((unsigned)c4.z < (unsigned)N_NODES) atomicAdd(&g_degi[c4.z], 1);
            if ((unsigned)c4.w < (unsigned)N_NODES) atomicAdd(&g_degi[c4.w], 1);
        } else {
            for (int e = base; e < N_EDGES; e++) {
                int c = col[e];
                if ((unsigned)c < (unsigned)N_NODES) atomicAdd(&g_degi[c], 1);
            }
        }
    } else {
        gemm_body<false>(x, W0, blockIdx.x - GE4_BLOCKS, Ws);
    }
}

// standalone GEMM for layers 2,3 (reads g_h16)
__global__ void gemm_h_kernel(const float* __restrict__ W) {
    __shared__ float4 Ws[DH * 16];
    gemm_body<true>(0, W, blockIdx.x, Ws);
}

// ---------------- prep scans ----------------
__global__ void scan1_kernel() {
    __shared__ int s[SCAN_B];
    int t = threadIdx.x;
    int i = blockIdx.x * SCAN_B + t;
    int v = (i < N_NODES) ? g_degi[i] : 0;
    if (i < N_NODES) {
        g_dinv[i] = rsqrtf((float)v + 1.0f);   // +1 self loop
        g_degi[i] = 0;                         // clear for next run
    }
    s[t] = v;
    __syncthreads();
#pragma unroll
    for (int d = 1; d < SCAN_B; d <<= 1) {
        int u = (t >= d) ? s[t - d] : 0;
        __syncthreads();
        s[t] += u;
        __syncthreads();
    }
    if (i < N_NODES) g_off[i] = s[t] - v;
    if (t == SCAN_B - 1) g_bsum[blockIdx.x] = s[t];
}

__global__ void scan3_kernel(const int* __restrict__ batch) {
    __shared__ int s[128];
    int t = threadIdx.x;  // 256 threads
    if (t < 128) {
        int v = (t < SCAN_NBLK) ? g_bsum[t] : 0;
        s[t] = v;
    }
    __syncthreads();
#pragma unroll
    for (int d = 1; d < 128; d <<= 1) {
        int u = 0;
        if (t < 128 && t >= d) u = s[t - d];
        __syncthreads();
        if (t < 128) s[t] += u;
        __syncthreads();
    }
    int i = blockIdx.x * blockDim.x + t;
    if (i < N_NODES) {
        int blk = i / SCAN_B;
        int pre = s[blk] - g_bsum[blk];
        int off = g_off[i] + pre;
        g_off[i] = off;
        g_cur[i] = off;
        if (i == 0) g_off[N_NODES] = s[127];

        int b  = batch[i];
        int bp = (i == 0) ? -1 : batch[i - 1];
        if (b < 0) b = 0;
        if (b >= NG) b = NG - 1;
        if (bp < -1) bp = -1;
        if (bp >= NG) bp = NG - 1;
        for (int g = bp + 1; g <= b; g++) g_start[g] = i;
        if (i == N_NODES - 1)
            for (int g = b + 1; g <= NG; g++) g_start[g] = N_NODES;
    }
}

// 4 edges/thread: 4 independent cursor atomics in flight before the stores
__global__ void scatter_kernel(const int* __restrict__ ei) {
    int base = (blockIdx.x * TB + threadIdx.x) * 4;
    if (base + 3 < N_EDGES) {
        int4 r4 = *(const int4*)(ei + base);
        int4 c4 = *(const int4*)(ei + N_EDGES + base);
        int r[4] = {r4.x, r4.y, r4.z, r4.w};
        int c[4] = {c4.x, c4.y, c4.z, c4.w};
        int pos[4];
        bool ok[4];
#pragma unroll
        for (int q = 0; q < 4; q++) {
            ok[q] = (unsigned)r[q] < (unsigned)N_NODES &&
                    (unsigned)c[q] < (unsigned)N_NODES;
            pos[q] = ok[q] ? atomicAdd(&g_cur[c[q]], 1) : 0;
        }
#pragma unroll
        for (int q = 0; q < 4; q++)
            if (ok[q]) g_edge[pos[q]] = (unsigned short)r[q];
    } else {
        for (int e = base; e < N_EDGES; e++) {
            int r = ei[e];
            int c = ei[N_EDGES + e];
            if ((unsigned)r >= (unsigned)N_NODES || (unsigned)c >= (unsigned)N_NODES)
                continue;
            int pos = atomicAdd(&g_cur[c], 1);
            g_edge[pos] = (unsigned short)r;
        }
    }
}

// ---------------- fused aggregate: h16 = relu(csr_sum + selfloop + bias) --
__global__ void agg_kernel(const float* __restrict__ bias) {
    int tid  = blockIdx.x * blockDim.x + threadIdx.x;
    int node = tid >> 4;
    int f    = tid & 15;
    if (node >= N_NODES) return;

    int beg = g_off[node];
    int end = g_off[node + 1];
    float di = g_dinv[node];

    float2 sa, sb;
    upk_h4(g_t16[node * 16 + f], sa, sb);
    float s = di * di;
    float4 acc = make_float4(sa.x * s, sa.y * s, sb.x * s, sb.y * s);

    int j = beg;
    for (; j + 7 < end; j += 8) {   // 8-deep for MLP
        int   ee[8];
        float dd[8];
        uint2 uu[8];
#pragma unroll
        for (int q = 0; q < 8; q++) ee[q] = g_edge[j + q];
#pragma unroll
        for (int q = 0; q < 8; q++) dd[q] = g_dinv[ee[q]];
#pragma unroll
        for (int q = 0; q < 8; q++) uu[q] = g_t16[ee[q] * 16 + f];
#pragma unroll
        for (int q = 0; q < 8; q++) {
            float2 a, b;
            upk_h4(uu[q], a, b);
            float w = di * dd[q];
            acc.x = fmaf(w, a.x, acc.x); acc.y = fmaf(w, a.y, acc.y);
            acc.z = fmaf(w, b.x, acc.z); acc.w = fmaf(w, b.y, acc.w);
        }
    }
    for (; j < end; j++) {
        int src = g_edge[j];
        float2 a, b;
        upk_h4(g_t16[src * 16 + f], a, b);
        float w = di * g_dinv[src];
        acc.x = fmaf(w, a.x, acc.x); acc.y = fmaf(w, a.y, acc.y);
        acc.z = fmaf(w, b.x, acc.z); acc.w = fmaf(w, b.y, acc.w);
    }

    float4 b4 = ((const float4*)bias)[f];
    g_h16[node * 16 + f] = pk_h4(fmaxf(acc.x + b4.x, 0.f),
                                 fmaxf(acc.y + b4.y, 0.f),
                                 fmaxf(acc.z + b4.z, 0.f),
                                 fmaxf(acc.w + b4.w, 0.f));
}

// ---------------- pooling (fp32 accumulation over fp16 h) -----------------
__global__ void pool_kernel(float* __restrict__ out) {
    __shared__ float4 sm[256];
    int g  = blockIdx.x;
    int t  = threadIdx.x;
    int f  = t & 15;
    int r0 = t >> 4;
    int beg = g_start[g];
    int end = g_start[g + 1];

    float4 acc = make_float4(0.f, 0.f, 0.f, 0.f);
    for (int r = beg + r0; r < end; r += 16) {
        float2 a, b;
        upk_h4(g_h16[r * 16 + f], a, b);
        acc.x += a.x; acc.y += a.y; acc.z += b.x; acc.w += b.y;
    }
    sm[t] = acc;
    __syncthreads();
#pragma unroll
    for (int s = 8; s > 0; s >>= 1) {
        if (r0 < s) {
            float4 o = sm[t + s * 16];
            float4 m = sm[t];
            sm[t] = make_float4(m.x + o.x, m.y + o.y, m.z + o.z, m.w + o.w);
        }
        __syncthreads();
    }
    if (r0 == 0) {
        float inv = 1.0f / fmaxf((float)(end - beg), 1.0f);
        float4 v = sm[f];
        v.x *= inv; v.y *= inv; v.z *= inv; v.w *= inv;
        ((float4*)out)[g * 16 + f] = v;
    }
}

// ---------------- launch: bind inputs BY ELEMENT COUNT --------------------
extern "C" void kernel_launch(void* const* d_in, const int* in_sizes, int n_in,
                              void* d_out, int out_size) {
    const float* x     = 0;
    const int*   ei    = 0;
    const int*   batch = 0;
    const float* W[3] = {0, 0, 0};
    const float* B[3] = {0, 0, 0};
    int nw = 0, nb = 0;

    for (int i = 0; i < n_in; i++) {
        int sz = in_sizes[i];
        if      (sz == N_NODES * DH)  x     = (const float*)d_in[i];
        else if (sz == 2 * N_EDGES)   ei    = (const int*)d_in[i];
        else if (sz == N_NODES)       batch = (const int*)d_in[i];
        else if (sz == DH * DH) { if (nw < 3) W[nw++] = (const float*)d_in[i]; }
        else if (sz == DH)      { if (nb < 3) B[nb++] = (const float*)d_in[i]; }
    }
    if (!x || !ei || !batch || nw != 3 || nb != 3) return;

    float* out = (float*)d_out;

    const int gN    = (N_NODES + TB - 1) / TB;         // 196
    const int gN16  = (N_NODES * 16 + TB - 1) / TB;    // 3125

    // ---- prep (deg overlapped with layer-1 GEMM) ----
    deg_gemm1_kernel<<<GE4_BLOCKS + GQ_BLOCKS, TB>>>(ei + N_EDGES, x, W[0]);
    scan1_kernel<<<SCAN_NBLK, SCAN_B>>>();
    scan3_kernel<<<gN, TB>>>(batch);
    scatter_kernel<<<GE4_BLOCKS, TB>>>(ei);

    // ---- layers ----
    agg_kernel<<<gN16, TB>>>(B[0]);
    gemm_h_kernel<<<GQ_BLOCKS, TB>>>(W[1]);
    agg_kernel<<<gN16, TB>>>(B[1]);
    gemm_h_kernel<<<GQ_BLOCKS, TB>>>(W[2]);
    agg_kernel<<<gN16, TB>>>(B[2]);

    // ---- global mean pool ----
    pool_kernel<<<NG, 256>>>(out);
}

// round 15
// speedup vs baseline: 1.0653x; 1.0653x over previous
#include <cuda_runtime.h>
#include <cuda_fp16.h>

#define N_NODES 50000
#define N_EDGES 800000
#define DH 64
#define NG 64

#define SCAN_B 512
#define SCAN_NBLK ((N_NODES + SCAN_B - 1) / SCAN_B)   // 98

#define TB 256
#define GE_BLOCKS ((N_EDGES + TB - 1) / TB)                    // 3125
#define GQ_BLOCKS ((N_NODES / 4 * 16 + TB - 1) / TB)           // 782

// ---------------- device scratch ----------------
__device__ float          g_dinv[N_NODES];
__device__ int            g_degi[N_NODES];   // zero-init; re-zeroed by scan1
__device__ int            g_off[N_NODES + 1];
__device__ int            g_cur[N_NODES];
__device__ int            g_bsum[SCAN_NBLK];
__device__ unsigned short g_edge[N_EDGES];   // src index (fits: N_NODES < 65536)
__device__ uint2          g_t16[N_NODES * 16];
__device__ uint2          g_h16[N_NODES * 16];
__device__ int            g_start[NG + 1];

// packed f32x2 helpers (Blackwell dual-FP32 pipe; PTX-only)
__device__ __forceinline__ unsigned long long pk2(float a, float b) {
    unsigned long long r;
    asm("mov.b64 %0, {%1, %2};" : "=l"(r) : "f"(a), "f"(b));
    return r;
}
__device__ __forceinline__ void fma2(unsigned long long& d,
                                     unsigned long long a, unsigned long long b) {
    asm("fma.rn.f32x2 %0, %1, %2, %0;" : "+l"(d) : "l"(a), "l"(b));
}
__device__ __forceinline__ float2 upk2(unsigned long long v) {
    float2 f;
    asm("mov.b64 {%0, %1}, %2;" : "=f"(f.x), "=f"(f.y) : "l"(v));
    return f;
}
__device__ __forceinline__ void upk_h4(uint2 u, float2& a, float2& b) {
    a = __half22float2(*(const __half2*)&u.x);
    b = __half22float2(*(const __half2*)&u.y);
}
__device__ __forceinline__ uint2 pk_h4(float x, float y, float z, float w) {
    __half2 h01 = __floats2half2_rn(x, y);
    __half2 h23 = __floats2half2_rn(z, w);
    uint2 u;
    u.x = *(const unsigned int*)&h01;
    u.y = *(const unsigned int*)&h23;
    return u;
}

// ---------------- GEMM body -------------------------------------------------
// PRESCALE: multiply output row by dinv[node] (for layers whose agg uses the
// prescaled identity h = relu(b + dinv[n]*(sum t'[src] + t'[n]))).
template <bool USEH, bool PRESCALE>
__device__ __forceinline__ void gemm_body(const float* __restrict__ in,
                                          const float* __restrict__ W,
                                          int gbid, float4* Ws) {
    const float4* W4 = (const float4*)W;
    for (int i = threadIdx.x; i < DH * 16; i += TB) Ws[i] = W4[i];
    __syncthreads();

    int tid  = gbid * TB + threadIdx.x;
    int quad = tid >> 4;
    int g    = tid & 15;
    int node0 = quad * 4;
    if (node0 >= N_NODES) return;

    unsigned long long acc01[4] = {0, 0, 0, 0};
    unsigned long long acc23[4] = {0, 0, 0, 0};

#pragma unroll
    for (int k4 = 0; k4 < 16; k4++) {
        float4 xv[4];
#pragma unroll
        for (int i = 0; i < 4; i++) {
            if (USEH) {
                float2 a, b;
                upk_h4(g_h16[(node0 + i) * 16 + k4], a, b);
                xv[i] = make_float4(a.x, a.y, b.x, b.y);
            } else {
                xv[i] = ((const float4*)in)[(node0 + i) * 16 + k4];
            }
        }
#pragma unroll
        for (int s = 0; s < 4; s++) {
            float4 w = Ws[(k4 * 4 + s) * 16 + g];
            unsigned long long w01 = pk2(w.x, w.y);
            unsigned long long w23 = pk2(w.z, w.w);
#pragma unroll
            for (int i = 0; i < 4; i++) {
                float xk = (s == 0) ? xv[i].x : (s == 1) ? xv[i].y
                         : (s == 2) ? xv[i].z : xv[i].w;
                unsigned long long xx = pk2(xk, xk);
                fma2(acc01[i], w01, xx);
                fma2(acc23[i], w23, xx);
            }
        }
    }
#pragma unroll
    for (int i = 0; i < 4; i++) {
        float2 lo = upk2(acc01[i]);
        float2 hi = upk2(acc23[i]);
        if (PRESCALE) {
            float dv = g_dinv[node0 + i];
            lo.x *= dv; lo.y *= dv; hi.x *= dv; hi.y *= dv;
        }
        g_t16[(node0 + i) * 16 + g] = pk_h4(lo.x, lo.y, hi.x, hi.y);
    }
}

// ---------------- fat kernel: degree histogram ∥ layer-1 GEMM (raw t) ------
__global__ void deg_gemm1_kernel(const int* __restrict__ col,
                                 const float* __restrict__ x,
                                 const float* __restrict__ W0) {
    __shared__ float4 Ws[DH * 16];  // 16 KB (gemm half only)
    if (blockIdx.x < GE_BLOCKS) {
        int e = blockIdx.x * TB + threadIdx.x;
        if (e < N_EDGES) {
            int c = col[e];
            if ((unsigned)c < (unsigned)N_NODES) atomicAdd(&g_degi[c], 1);  // REDG
        }
    } else {
        gemm_body<false, false>(x, W0, blockIdx.x - GE_BLOCKS, Ws);
    }
}

// standalone GEMM for layers 2,3 (reads g_h16, writes prescaled t')
__global__ void gemm_h_kernel(const float* __restrict__ W) {
    __shared__ float4 Ws[DH * 16];
    gemm_body<true, true>(0, W, blockIdx.x, Ws);
}

// ---------------- prep scans ----------------
__global__ void scan1_kernel() {
    __shared__ int s[SCAN_B];
    int t = threadIdx.x;
    int i = blockIdx.x * SCAN_B + t;
    int v = (i < N_NODES) ? g_degi[i] : 0;
    if (i < N_NODES) {
        g_dinv[i] = rsqrtf((float)v + 1.0f);   // +1 self loop
        g_degi[i] = 0;                         // clear for next run
    }
    s[t] = v;
    __syncthreads();
#pragma unroll
    for (int d = 1; d < SCAN_B; d <<= 1) {
        int u = (t >= d) ? s[t - d] : 0;
        __syncthreads();
        s[t] += u;
        __syncthreads();
    }
    if (i < N_NODES) g_off[i] = s[t] - v;
    if (t == SCAN_B - 1) g_bsum[blockIdx.x] = s[t];
}

__global__ void scan3_kernel(const int* __restrict__ batch) {
    __shared__ int s[128];
    int t = threadIdx.x;  // 256 threads
    if (t < 128) {
        int v = (t < SCAN_NBLK) ? g_bsum[t] : 0;
        s[t] = v;
    }
    __syncthreads();
#pragma unroll
    for (int d = 1; d < 128; d <<= 1) {
        int u = 0;
        if (t < 128 && t >= d) u = s[t - d];
        __syncthreads();
        if (t < 128) s[t] += u;
        __syncthreads();
    }
    int i = blockIdx.x * blockDim.x + t;
    if (i < N_NODES) {
        int blk = i / SCAN_B;
        int pre = s[blk] - g_bsum[blk];
        int off = g_off[i] + pre;
        g_off[i] = off;
        g_cur[i] = off;
        if (i == 0) g_off[N_NODES] = s[127];

        int b  = batch[i];
        int bp = (i == 0) ? -1 : batch[i - 1];
        if (b < 0) b = 0;
        if (b >= NG) b = NG - 1;
        if (bp < -1) bp = -1;
        if (bp >= NG) bp = NG - 1;
        for (int g = bp + 1; g <= b; g++) g_start[g] = i;
        if (i == N_NODES - 1)
            for (int g = b + 1; g <= NG; g++) g_start[g] = N_NODES;
    }
}

// 1 edge/thread cursor scatter (measured floor for contended ATOMG)
__global__ void scatter_kernel(const int* __restrict__ ei) {
    int e = blockIdx.x * blockDim.x + threadIdx.x;
    if (e >= N_EDGES) return;
    int r = ei[e];
    int c = ei[N_EDGES + e];
    if ((unsigned)r >= (unsigned)N_NODES || (unsigned)c >= (unsigned)N_NODES)
        return;
    int pos = atomicAdd(&g_cur[c], 1);
    g_edge[pos] = (unsigned short)r;
}

// ---------------- fused aggregate ------------------------------------------
// PRESCALED=false (layer 1): t is raw; weight = dinv[n]*dinv[src] per edge.
// PRESCALED=true (layers 2,3): t' = dinv*t; h = relu(b + dinv[n]*(sum + t'[n])).
template <bool PRESCALED>
__global__ void agg_kernel(const float* __restrict__ bias) {
    int tid  = blockIdx.x * blockDim.x + threadIdx.x;
    int node = tid >> 4;
    int f    = tid & 15;
    if (node >= N_NODES) return;

    int beg = g_off[node];
    int end = g_off[node + 1];
    float di = g_dinv[node];

    float2 sa, sb;
    upk_h4(g_t16[node * 16 + f], sa, sb);
    float4 acc;
    if (PRESCALED) {
        acc = make_float4(sa.x, sa.y, sb.x, sb.y);        // t'[n]; × di at end
    } else {
        float s = di * di;
        acc = make_float4(sa.x * s, sa.y * s, sb.x * s, sb.y * s);
    }

    int j = beg;
    for (; j + 7 < end; j += 8) {
        int   ee[8];
        uint2 uu[8];
        float dd[8];
#pragma unroll
        for (int q = 0; q < 8; q++) ee[q] = g_edge[j + q];
        if (!PRESCALED) {
#pragma unroll
            for (int q = 0; q < 8; q++) dd[q] = g_dinv[ee[q]];
        }
#pragma unroll
        for (int q = 0; q < 8; q++) uu[q] = g_t16[ee[q] * 16 + f];
#pragma unroll
        for (int q = 0; q < 8; q++) {
            float2 a, b;
            upk_h4(uu[q], a, b);
            if (PRESCALED) {
                acc.x += a.x; acc.y += a.y; acc.z += b.x; acc.w += b.y;
            } else {
                float w = di * dd[q];
                acc.x = fmaf(w, a.x, acc.x); acc.y = fmaf(w, a.y, acc.y);
                acc.z = fmaf(w, b.x, acc.z); acc.w = fmaf(w, b.y, acc.w);
            }
        }
    }
    for (; j < end; j++) {
        int src = g_edge[j];
        float2 a, b;
        upk_h4(g_t16[src * 16 + f], a, b);
        if (PRESCALED) {
            acc.x += a.x; acc.y += a.y; acc.z += b.x; acc.w += b.y;
        } else {
            float w = di * g_dinv[src];
            acc.x = fmaf(w, a.x, acc.x); acc.y = fmaf(w, a.y, acc.y);
            acc.z = fmaf(w, b.x, acc.z); acc.w = fmaf(w, b.y, acc.w);
        }
    }

    if (PRESCALED) {
        acc.x *= di; acc.y *= di; acc.z *= di; acc.w *= di;
    }
    float4 b4 = ((const float4*)bias)[f];
    g_h16[node * 16 + f] = pk_h4(fmaxf(acc.x + b4.x, 0.f),
                                 fmaxf(acc.y + b4.y, 0.f),
                                 fmaxf(acc.z + b4.z, 0.f),
                                 fmaxf(acc.w + b4.w, 0.f));
}

// ---------------- pooling (fp32 accumulation over fp16 h) -----------------
__global__ void pool_kernel(float* __restrict__ out) {
    __shared__ float4 sm[256];
    int g  = blockIdx.x;
    int t  = threadIdx.x;
    int f  = t & 15;
    int r0 = t >> 4;
    int beg = g_start[g];
    int end = g_start[g + 1];

    float4 acc = make_float4(0.f, 0.f, 0.f, 0.f);
    for (int r = beg + r0; r < end; r += 16) {
        float2 a, b;
        upk_h4(g_h16[r * 16 + f], a, b);
        acc.x += a.x; acc.y += a.y; acc.z += b.x; acc.w += b.y;
    }
    sm[t] = acc;
    __syncthreads();
#pragma unroll
    for (int s = 8; s > 0; s >>= 1) {
        if (r0 < s) {
            float4 o = sm[t + s * 16];
            float4 m = sm[t];
            sm[t] = make_float4(m.x + o.x, m.y + o.y, m.z + o.z, m.w + o.w);
        }
        __syncthreads();
    }
    if (r0 == 0) {
        float inv = 1.0f / fmaxf((float)(end - beg), 1.0f);
        float4 v = sm[f];
        v.x *= inv; v.y *= inv; v.z *= inv; v.w *= inv;
        ((float4*)out)[g * 16 + f] = v;
    }
}

// ---------------- launch: bind inputs BY ELEMENT COUNT --------------------
extern "C" void kernel_launch(void* const* d_in, const int* in_sizes, int n_in,
                              void* d_out, int out_size) {
    const float* x     = 0;
    const int*   ei    = 0;
    const int*   batch = 0;
    const float* W[3] = {0, 0, 0};
    const float* B[3] = {0, 0, 0};
    int nw = 0, nb = 0;

    for (int i = 0; i < n_in; i++) {
        int sz = in_sizes[i];
        if      (sz == N_NODES * DH)  x     = (const float*)d_in[i];
        else if (sz == 2 * N_EDGES)   ei    = (const int*)d_in[i];
        else if (sz == N_NODES)       batch = (const int*)d_in[i];
        else if (sz == DH * DH) { if (nw < 3) W[nw++] = (const float*)d_in[i]; }
        else if (sz == DH)      { if (nb < 3) B[nb++] = (const float*)d_in[i]; }
    }
    if (!x || !ei || !batch || nw != 3 || nb != 3) return;

    float* out = (float*)d_out;

    const int gN    = (N_NODES + TB - 1) / TB;         // 196
    const int gN16  = (N_NODES * 16 + TB - 1) / TB;    // 3125

    // ---- prep (deg overlapped with layer-1 GEMM) ----
    deg_gemm1_kernel<<<GE_BLOCKS + GQ_BLOCKS, TB>>>(ei + N_EDGES, x, W[0]);
    scan1_kernel<<<SCAN_NBLK, SCAN_B>>>();
    scan3_kernel<<<gN, TB>>>(batch);
    scatter_kernel<<<GE_BLOCKS, TB>>>(ei);

    // ---- layers ----
    agg_kernel<false><<<gN16, TB>>>(B[0]);
    gemm_h_kernel<<<GQ_BLOCKS, TB>>>(W[1]);
    agg_kernel<true><<<gN16, TB>>>(B[1]);
    gemm_h_kernel<<<GQ_BLOCKS, TB>>>(W[2]);
    agg_kernel<true><<<gN16, TB>>>(B[2]);

    // ---- global mean pool ----
    pool_kernel<<<NG, 256>>>(out);
}

// round 16
// speedup vs baseline: 1.0830x; 1.0166x over previous
#include <cuda_runtime.h>
#include <cuda_fp16.h>

#define N_NODES 50000
#define N_EDGES 800000
#define DH 64
#define NG 64

#define SCAN_B 512
#define SCAN_NBLK ((N_NODES + SCAN_B - 1) / SCAN_B)   // 98

#define TB 256
#define GE_BLOCKS ((N_EDGES + TB - 1) / TB)                    // 3125
#define GQ_BLOCKS ((N_NODES / 4 * 16 + TB - 1) / TB)           // 782

// ---------------- device scratch ----------------
__device__ float          g_dinv[N_NODES];
__device__ int            g_degi[N_NODES];   // zero-init; re-zeroed by scan1
__device__ int            g_off[N_NODES + 1];
__device__ int            g_cur[N_NODES];
__device__ int            g_bsum[SCAN_NBLK]; // lookback slots (0 = not ready); reset by scatter
__device__ unsigned short g_edge[N_EDGES];   // src index (fits: N_NODES < 65536)
__device__ uint2          g_t16[N_NODES * 16];
__device__ uint2          g_h16[N_NODES * 16];
__device__ int            g_start[NG + 1];

// packed f32x2 helpers (Blackwell dual-FP32 pipe; PTX-only)
__device__ __forceinline__ unsigned long long pk2(float a, float b) {
    unsigned long long r;
    asm("mov.b64 %0, {%1, %2};" : "=l"(r) : "f"(a), "f"(b));
    return r;
}
__device__ __forceinline__ void fma2(unsigned long long& d,
                                     unsigned long long a, unsigned long long b) {
    asm("fma.rn.f32x2 %0, %1, %2, %0;" : "+l"(d) : "l"(a), "l"(b));
}
__device__ __forceinline__ float2 upk2(unsigned long long v) {
    float2 f;
    asm("mov.b64 {%0, %1}, %2;" : "=f"(f.x), "=f"(f.y) : "l"(v));
    return f;
}
__device__ __forceinline__ void upk_h4(uint2 u, float2& a, float2& b) {
    a = __half22float2(*(const __half2*)&u.x);
    b = __half22float2(*(const __half2*)&u.y);
}
__device__ __forceinline__ uint2 pk_h4(float x, float y, float z, float w) {
    __half2 h01 = __floats2half2_rn(x, y);
    __half2 h23 = __floats2half2_rn(z, w);
    uint2 u;
    u.x = *(const unsigned int*)&h01;
    u.y = *(const unsigned int*)&h23;
    return u;
}

// ---------------- GEMM body -------------------------------------------------
template <bool USEH, bool PRESCALE>
__device__ __forceinline__ void gemm_body(const float* __restrict__ in,
                                          const float* __restrict__ W,
                                          int gbid, float4* Ws) {
    const float4* W4 = (const float4*)W;
    for (int i = threadIdx.x; i < DH * 16; i += TB) Ws[i] = W4[i];
    __syncthreads();

    int tid  = gbid * TB + threadIdx.x;
    int quad = tid >> 4;
    int g    = tid & 15;
    int node0 = quad * 4;
    if (node0 >= N_NODES) return;

    unsigned long long acc01[4] = {0, 0, 0, 0};
    unsigned long long acc23[4] = {0, 0, 0, 0};

#pragma unroll
    for (int k4 = 0; k4 < 16; k4++) {
        float4 xv[4];
#pragma unroll
        for (int i = 0; i < 4; i++) {
            if (USEH) {
                float2 a, b;
                upk_h4(g_h16[(node0 + i) * 16 + k4], a, b);
                xv[i] = make_float4(a.x, a.y, b.x, b.y);
            } else {
                xv[i] = ((const float4*)in)[(node0 + i) * 16 + k4];
            }
        }
#pragma unroll
        for (int s = 0; s < 4; s++) {
            float4 w = Ws[(k4 * 4 + s) * 16 + g];
            unsigned long long w01 = pk2(w.x, w.y);
            unsigned long long w23 = pk2(w.z, w.w);
#pragma unroll
            for (int i = 0; i < 4; i++) {
                float xk = (s == 0) ? xv[i].x : (s == 1) ? xv[i].y
                         : (s == 2) ? xv[i].z : xv[i].w;
                unsigned long long xx = pk2(xk, xk);
                fma2(acc01[i], w01, xx);
                fma2(acc23[i], w23, xx);
            }
        }
    }
#pragma unroll
    for (int i = 0; i < 4; i++) {
        float2 lo = upk2(acc01[i]);
        float2 hi = upk2(acc23[i]);
        if (PRESCALE) {
            float dv = g_dinv[node0 + i];
            lo.x *= dv; lo.y *= dv; hi.x *= dv; hi.y *= dv;
        }
        g_t16[(node0 + i) * 16 + g] = pk_h4(lo.x, lo.y, hi.x, hi.y);
    }
}

// ---------------- fat kernel: degree histogram ∥ layer-1 GEMM (raw t) ------
__global__ void deg_gemm1_kernel(const int* __restrict__ col,
                                 const float* __restrict__ x,
                                 const float* __restrict__ W0) {
    __shared__ float4 Ws[DH * 16];  // 16 KB (gemm half only)
    if (blockIdx.x < GE_BLOCKS) {
        int e = blockIdx.x * TB + threadIdx.x;
        if (e < N_EDGES) {
            int c = col[e];
            if ((unsigned)c < (unsigned)N_NODES) atomicAdd(&g_degi[c], 1);  // REDG
        }
    } else {
        gemm_body<false, false>(x, W0, blockIdx.x - GE_BLOCKS, Ws);
    }
}

// standalone GEMM for layers 2,3 (reads g_h16, writes prescaled t')
__global__ void gemm_h_kernel(const float* __restrict__ W) {
    __shared__ float4 Ws[DH * 16];
    gemm_body<true, true>(0, W, blockIdx.x, Ws);
}

// ---------------- single-pass scan with decoupled lookback -----------------
// 98 blocks, all resident (< 148 SMs, sole kernel): each publishes its chunk
// total (+1 so 0 = not ready), spins on all predecessors in parallel, and
// writes FINAL offsets + cursor. Also: dinv, degi re-zero, graph bounds.
__global__ void scan1_kernel(const int* __restrict__ batch) {
    __shared__ int s[SCAN_B];
    __shared__ int s_pre;
    int t = threadIdx.x;
    int blk = blockIdx.x;
    int i = blk * SCAN_B + t;
    int v = (i < N_NODES) ? g_degi[i] : 0;
    if (i < N_NODES) {
        g_dinv[i] = rsqrtf((float)v + 1.0f);   // +1 self loop
        g_degi[i] = 0;                         // clear for next run
    }
    if (t == 0) s_pre = 0;
    s[t] = v;
    __syncthreads();
#pragma unroll
    for (int d = 1; d < SCAN_B; d <<= 1) {
        int u = (t >= d) ? s[t - d] : 0;
        __syncthreads();
        s[t] += u;
        __syncthreads();
    }
    // publish own total, then gather predecessors' totals in parallel
    if (t == SCAN_B - 1) atomicExch(&g_bsum[blk], s[t] + 1);
    if (t < blk) {  // t < 98
        int vv;
        do { vv = *((volatile int*)&g_bsum[t]); } while (vv == 0);
        atomicAdd(&s_pre, vv - 1);
    }
    __syncthreads();
    int pre = s_pre;

    if (i < N_NODES) {
        int off = pre + s[t] - v;    // global exclusive prefix
        g_off[i] = off;
        g_cur[i] = off;

        // graph boundaries (sorted batch)
        int b  = batch[i];
        int bp = (i == 0) ? -1 : batch[i - 1];
        if (b < 0) b = 0;
        if (b >= NG) b = NG - 1;
        if (bp < -1) bp = -1;
        if (bp >= NG) bp = NG - 1;
        for (int g = bp + 1; g <= b; g++) g_start[g] = i;
        if (i == N_NODES - 1)
            for (int g = b + 1; g <= NG; g++) g_start[g] = N_NODES;
    }
    if (blk == SCAN_NBLK - 1 && t == SCAN_B - 1)
        g_off[N_NODES] = pre + s[t];
}

// 1 edge/thread cursor scatter (measured floor) + g_bsum reset for next run
__global__ void scatter_kernel(const int* __restrict__ ei) {
    int e = blockIdx.x * blockDim.x + threadIdx.x;
    if (blockIdx.x == 0 && threadIdx.x < SCAN_NBLK)
        g_bsum[threadIdx.x] = 0;               // lookback slots must be 0 next run
    if (e >= N_EDGES) return;
    int r = ei[e];
    int c = ei[N_EDGES + e];
    if ((unsigned)r >= (unsigned)N_NODES || (unsigned)c >= (unsigned)N_NODES)
        return;
    int pos = atomicAdd(&g_cur[c], 1);
    g_edge[pos] = (unsigned short)r;
}

// ---------------- fused aggregate ------------------------------------------
template <bool PRESCALED>
__global__ void agg_kernel(const float* __restrict__ bias) {
    int tid  = blockIdx.x * blockDim.x + threadIdx.x;
    int node = tid >> 4;
    int f    = tid & 15;
    if (node >= N_NODES) return;

    int beg = g_off[node];
    int end = g_off[node + 1];
    float di = g_dinv[node];

    float2 sa, sb;
    upk_h4(g_t16[node * 16 + f], sa, sb);
    float4 acc;
    if (PRESCALED) {
        acc = make_float4(sa.x, sa.y, sb.x, sb.y);
    } else {
        float s = di * di;
        acc = make_float4(sa.x * s, sa.y * s, sb.x * s, sb.y * s);
    }

    int j = beg;
    for (; j + 7 < end; j += 8) {
        int   ee[8];
        uint2 uu[8];
        float dd[8];
#pragma unroll
        for (int q = 0; q < 8; q++) ee[q] = g_edge[j + q];
        if (!PRESCALED) {
#pragma unroll
            for (int q = 0; q < 8; q++) dd[q] = g_dinv[ee[q]];
        }
#pragma unroll
        for (int q = 0; q < 8; q++) uu[q] = g_t16[ee[q] * 16 + f];
#pragma unroll
        for (int q = 0; q < 8; q++) {
            float2 a, b;
            upk_h4(uu[q], a, b);
            if (PRESCALED) {
                acc.x += a.x; acc.y += a.y; acc.z += b.x; acc.w += b.y;
            } else {
                float w = di * dd[q];
                acc.x = fmaf(w, a.x, acc.x); acc.y = fmaf(w, a.y, acc.y);
                acc.z = fmaf(w, b.x, acc.z); acc.w = fmaf(w, b.y, acc.w);
            }
        }
    }
    for (; j < end; j++) {
        int src = g_edge[j];
        float2 a, b;
        upk_h4(g_t16[src * 16 + f], a, b);
        if (PRESCALED) {
            acc.x += a.x; acc.y += a.y; acc.z += b.x; acc.w += b.y;
        } else {
            float w = di * g_dinv[src];
            acc.x = fmaf(w, a.x, acc.x); acc.y = fmaf(w, a.y, acc.y);
            acc.z = fmaf(w, b.x, acc.z); acc.w = fmaf(w, b.y, acc.w);
        }
    }

    if (PRESCALED) {
        acc.x *= di; acc.y *= di; acc.z *= di; acc.w *= di;
    }
    float4 b4 = ((const float4*)bias)[f];
    g_h16[node * 16 + f] = pk_h4(fmaxf(acc.x + b4.x, 0.f),
                                 fmaxf(acc.y + b4.y, 0.f),
                                 fmaxf(acc.z + b4.z, 0.f),
                                 fmaxf(acc.w + b4.w, 0.f));
}

// ---------------- pooling (fp32 accumulation over fp16 h) -----------------
__global__ void pool_kernel(float* __restrict__ out) {
    __shared__ float4 sm[256];
    int g  = blockIdx.x;
    int t  = threadIdx.x;
    int f  = t & 15;
    int r0 = t >> 4;
    int beg = g_start[g];
    int end = g_start[g + 1];

    float4 acc = make_float4(0.f, 0.f, 0.f, 0.f);
    for (int r = beg + r0; r < end; r += 16) {
        float2 a, b;
        upk_h4(g_h16[r * 16 + f], a, b);
        acc.x += a.x; acc.y += a.y; acc.z += b.x; acc.w += b.y;
    }
    sm[t] = acc;
    __syncthreads();
#pragma unroll
    for (int s = 8; s > 0; s >>= 1) {
        if (r0 < s) {
            float4 o = sm[t + s * 16];
            float4 m = sm[t];
            sm[t] = make_float4(m.x + o.x, m.y + o.y, m.z + o.z, m.w + o.w);
        }
        __syncthreads();
    }
    if (r0 == 0) {
        float inv = 1.0f / fmaxf((float)(end - beg), 1.0f);
        float4 v = sm[f];
        v.x *= inv; v.y *= inv; v.z *= inv; v.w *= inv;
        ((float4*)out)[g * 16 + f] = v;
    }
}

// ---------------- launch: bind inputs BY ELEMENT COUNT --------------------
extern "C" void kernel_launch(void* const* d_in, const int* in_sizes, int n_in,
                              void* d_out, int out_size) {
    const float* x     = 0;
    const int*   ei    = 0;
    const int*   batch = 0;
    const float* W[3] = {0, 0, 0};
    const float* B[3] = {0, 0, 0};
    int nw = 0, nb = 0;

    for (int i = 0; i < n_in; i++) {
        int sz = in_sizes[i];
        if      (sz == N_NODES * DH)  x     = (const float*)d_in[i];
        else if (sz == 2 * N_EDGES)   ei    = (const int*)d_in[i];
        else if (sz == N_NODES)       batch = (const int*)d_in[i];
        else if (sz == DH * DH) { if (nw < 3) W[nw++] = (const float*)d_in[i]; }
        else if (sz == DH)      { if (nb < 3) B[nb++] = (const float*)d_in[i]; }
    }
    if (!x || !ei || !batch || nw != 3 || nb != 3) return;

    float* out = (float*)d_out;

    const int gN16 = (N_NODES * 16 + TB - 1) / TB;    // 3125

    // ---- prep ----
    deg_gemm1_kernel<<<GE_BLOCKS + GQ_BLOCKS, TB>>>(ei + N_EDGES, x, W[0]);
    scan1_kernel<<<SCAN_NBLK, SCAN_B>>>(batch);       // single-pass scan
    scatter_kernel<<<GE_BLOCKS, TB>>>(ei);

    // ---- layers ----
    agg_kernel<false><<<gN16, TB>>>(B[0]);
    gemm_h_kernel<<<GQ_BLOCKS, TB>>>(W[1]);
    agg_kernel<true><<<gN16, TB>>>(B[1]);
    gemm_h_kernel<<<GQ_BLOCKS, TB>>>(W[2]);
    agg_kernel<true><<<gN16, TB>>>(B[2]);

    // ---- global mean pool ----
    pool_kernel<<<NG, 256>>>(out);
}